// round 16
// baseline (speedup 1.0000x reference)
#include <cuda_runtime.h>
#include <cuda_fp16.h>
#include <cstdint>
#include <cstddef>

#define N_VOX   200000
#define C_IN    128
#define D_MODEL 128
#define NY      400
#define NX      400
#define NB      4
#define PLANE   (NY*NX)        /* 160000 */
#define NPOS    (NB*PLANE)     /* 640000 */

#define NGROUP  8
#define GPOSN   80000          /* positions per group (= gather chunk) */
#define NCHUNK  8
#define CBLK    391            /* gemm blocks per chunk (64 slots each) */

typedef unsigned int u32;

// ---- device globals (zero-initialized at module load) ----
__device__ uint4 g_feath4[(size_t)N_VOX * 16];   // 51.2 MB fp16 feat, slot-indexed
__device__ int4  g_inv4[NPOS/4];                 // inv: 0 = empty, slot+1
__device__ int   g_list[N_VOX];                  // slot -> voxel id
__device__ int   g_cnt[NGROUP];
__device__ int   g_slotctr[NGROUP];

#define g_feath ((u32*)g_feath4)
#define g_inv   ((int*)g_inv4)

__device__ __forceinline__ uint4 round8h(float4 a, float4 b) {
    uint4 hi;
    __half2 h0 = __float22half2_rn(make_float2(a.x, a.y));
    __half2 h1 = __float22half2_rn(make_float2(a.z, a.w));
    __half2 h2 = __float22half2_rn(make_float2(b.x, b.y));
    __half2 h3 = __float22half2_rn(make_float2(b.z, b.w));
    hi.x = *(u32*)&h0; hi.y = *(u32*)&h1; hi.z = *(u32*)&h2; hi.w = *(u32*)&h3;
    return hi;
}
__device__ __forceinline__ u32 smem_u32(const void* p) {
    u32 a;
    asm("{ .reg .u64 t; cvta.to.shared.u64 t, %1; cvt.u32.u64 %0, t; }"
        : "=r"(a) : "l"(p));
    return a;
}
__device__ __forceinline__ void ldsm_x4(u32 addr, u32& r0, u32& r1, u32& r2, u32& r3) {
    asm volatile("ldmatrix.sync.aligned.m8n8.x4.shared.b16 {%0,%1,%2,%3}, [%4];"
                 : "=r"(r0), "=r"(r1), "=r"(r2), "=r"(r3) : "r"(addr));
}
__device__ __forceinline__ void mma16816h(float* c, const u32* a, const u32* b) {
    asm volatile(
        "mma.sync.aligned.m16n8k16.row.col.f32.f16.f16.f32 "
        "{%0,%1,%2,%3}, {%4,%5,%6,%7}, {%8,%9}, {%0,%1,%2,%3};"
        : "+f"(c[0]), "+f"(c[1]), "+f"(c[2]), "+f"(c[3])
        : "r"(a[0]), "r"(a[1]), "r"(a[2]), "r"(a[3]), "r"(b[0]), "r"(b[1]));
}
// per-warp coors dtype detect: int64 words [b,0,0,0,y,0,x,0] -> odd words zero
__device__ __forceinline__ bool detect64(const int* c32) {
    int l = threadIdx.x & 31;
    int v = c32[8 * l + 3] | c32[8 * l + 7];
    return (__ballot_sync(0xFFFFFFFFu, v != 0) == 0);
}
__device__ __forceinline__ int voxel_flat(const int* c32, int n, bool is64) {
    int b, y, x;
    if (is64) { b = c32[8*n + 0]; y = c32[8*n + 4]; x = c32[8*n + 6]; }
    else      { b = c32[4*n + 0]; y = c32[4*n + 2]; x = c32[4*n + 3]; }
    return b * PLANE + y * NX + x;
}

// ---- kernel 1: zero per-call counters ----
__global__ void k_init() {
    int t = threadIdx.x;
    if (t < NGROUP)                g_cnt[t] = 0;
    else if (t < 2 * NGROUP)       g_slotctr[t - NGROUP] = 0;
}

// ---- kernel 2: per-group voxel counts (smem-aggregated) ----
__global__ void k_count(const int* __restrict__ c32) {
    bool is64 = detect64(c32);
    __shared__ int sc[NGROUP];
    if (threadIdx.x < NGROUP) sc[threadIdx.x] = 0;
    __syncthreads();
    int n = blockIdx.x * 256 + threadIdx.x;
    if (n < N_VOX) atomicAdd(&sc[voxel_flat(c32, n, is64) / GPOSN], 1);
    __syncthreads();
    if (threadIdx.x < NGROUP && sc[threadIdx.x])
        atomicAdd(&g_cnt[threadIdx.x], sc[threadIdx.x]);
}

// ---- kernel 3: group-sorted slot assignment + inverse map ----
__global__ void k_fill(const int* __restrict__ c32) {
    bool is64 = detect64(c32);
    __shared__ int sc[NGROUP], sbase[NGROUP], sgb[NGROUP];
    int tid = threadIdx.x;
    if (tid < NGROUP) sc[tid] = 0;
    __syncthreads();
    int n = blockIdx.x * 256 + tid;
    int flat = 0, g = 0, myloc = -1;
    if (n < N_VOX) {
        flat = voxel_flat(c32, n, is64);
        g = flat / GPOSN;
        myloc = atomicAdd(&sc[g], 1);
    }
    __syncthreads();
    if (tid == 0) {
        int run = 0;
        #pragma unroll
        for (int i = 0; i < NGROUP; i++) { sgb[i] = run; run += g_cnt[i]; }
    }
    if (tid < NGROUP)
        sbase[tid] = (sc[tid] > 0) ? atomicAdd(&g_slotctr[tid], sc[tid]) : 0;
    __syncthreads();
    if (n < N_VOX) {
        int slot = sgb[g] + sbase[g] + myloc;
        g_list[slot] = n;
        g_inv[flat] = slot + 1;
    }
}

// ---- kernel 4: GEMM chunk over slot windows (r11 core, slot-indirected) ----
#define TSTRIDE 136
#define A_ELEMS (64 * TSTRIDE)    /* 17408 B */
#define W_ELEMS (128 * TSTRIDE)   /* 34816 B */
#define GEMM_SMEM ((A_ELEMS + W_ELEMS) * 2)   /* 52224 B */

__global__ __launch_bounds__(256, 3) void k_gemm(const float* __restrict__ V,
                                                 const float* __restrict__ W0,
                                                 const float* __restrict__ b0,
                                                 int block0) {
    extern __shared__ __align__(16) __half sm[];
    __half* Ah = sm;
    __half* Wh = sm + A_ELEMS;
    __shared__ int s_list[64];

    int tid = threadIdx.x, w = tid >> 5, lane = tid & 31;
    int slot_base = (block0 + blockIdx.x) * 64;   // 3125 blocks total: exact

    if (tid < 64) s_list[tid] = g_list[slot_base + tid];

    // stage W: W0 f32 (64KB, L2-resident) -> fp16 swizzled
    #pragma unroll
    for (int i = 0; i < 8; i++) {
        int x = tid + 256 * i;
        int n = x >> 4, j = x & 15;
        const float4* src = (const float4*)(W0 + n * 128 + 8 * j);
        *(uint4*)(Wh + n * TSTRIDE + 8 * j) = round8h(src[0], src[1]);
    }
    __syncthreads();

    // stage A via slot->voxel indirection; evict-first loads
    #pragma unroll
    for (int i = 0; i < 4; i++) {
        int x = tid + 256 * i;
        int r = x >> 4, j = x & 15;
        int n = s_list[r];
        const float4* src = (const float4*)(V + (size_t)n * 128 + 8 * j);
        float4 a = __ldcs(src), b = __ldcs(src + 1);
        *(uint4*)(Ah + r * TSTRIDE + 8 * j) = round8h(a, b);
    }
    __syncthreads();

    int wm = w & 1, wn = w >> 1;                // 2m x 4n warp grid
    float acc[2][4][4];
    #pragma unroll
    for (int mt = 0; mt < 2; mt++)
        #pragma unroll
        for (int nt = 0; nt < 4; nt++)
            #pragma unroll
            for (int q = 0; q < 4; q++) acc[mt][nt][q] = 0.f;

    int a_row = 32 * wm + (lane & 15);
    int b_row = 32 * wn + (lane & 15);
    int c_half = (lane >> 4) << 3;
    u32 ah_base = smem_u32(Ah), wh_base = smem_u32(Wh);

    #pragma unroll
    for (int ks = 0; ks < 8; ks++) {
        int kb = 16 * ks + c_half;
        u32 aH[2][4], bH[4][2];
        #pragma unroll
        for (int mt = 0; mt < 2; mt++) {
            u32 off = (u32)(((a_row + 16 * mt) * TSTRIDE + kb) * 2);
            ldsm_x4(ah_base + off, aH[mt][0], aH[mt][1], aH[mt][2], aH[mt][3]);
        }
        #pragma unroll
        for (int q = 0; q < 2; q++) {
            u32 off = (u32)(((b_row + 16 * q) * TSTRIDE + kb) * 2);
            u32 r0, r1, r2, r3;
            ldsm_x4(wh_base + off, r0, r1, r2, r3);
            bH[2*q][0] = r0; bH[2*q+1][0] = r1; bH[2*q][1] = r2; bH[2*q+1][1] = r3;
        }
        #pragma unroll
        for (int mt = 0; mt < 2; mt++)
            #pragma unroll
            for (int nt = 0; nt < 4; nt++)
                mma16816h(acc[mt][nt], aH[mt], bH[nt]);
    }

    // epilogue: bias + fp16 pack to slot-indexed feat rows
    int cp = 2 * (lane & 3);
    #pragma unroll
    for (int nt = 0; nt < 4; nt++) {
        int c = 32 * wn + 8 * nt + cp;
        float blo = __ldg(b0 + c), bhi = __ldg(b0 + c + 1);
        #pragma unroll
        for (int mt = 0; mt < 2; mt++) {
            int r0 = slot_base + 32 * wm + 16 * mt + (lane >> 2);
            __half2 h0 = __float22half2_rn(
                make_float2(acc[mt][nt][0] + blo, acc[mt][nt][1] + bhi));
            __half2 h1 = __float22half2_rn(
                make_float2(acc[mt][nt][2] + blo, acc[mt][nt][3] + bhi));
            g_feath[(size_t)r0 * 64 + (c >> 1)]       = *(u32*)&h0;
            g_feath[(size_t)(r0 + 8) * 64 + (c >> 1)] = *(u32*)&h1;
        }
    }
}

// ---- kernel 5: gather chunk (r11 gather, position-offset) ----
__global__ __launch_bounds__(256) void k_gath(float* __restrict__ out, int pos0) {
    __shared__ int s_inv[32];
    __shared__ u32 tile32[32 * 65];
    int base = pos0 + blockIdx.x * 32;
    int tid = threadIdx.x;
    if (tid < 32) s_inv[tid] = g_inv[base + tid];
    __syncthreads();
    int w = tid >> 5, l = tid & 31;
    #pragma unroll
    for (int i = 0; i < 4; i++) {
        int p = (w << 2) | i;
        int n = s_inv[p];                       // warp-uniform branch
        if (n > 0) {
            const u32* fr = g_feath + (size_t)(n - 1) * 64;
            tile32[p * 65 + l]      = fr[l];
            tile32[p * 65 + 32 + l] = fr[l + 32];
        } else {
            tile32[p * 65 + l]      = 0u;
            tile32[p * 65 + 32 + l] = 0u;
        }
    }
    __syncthreads();
    int b  = base / PLANE;
    int yx = base - b * PLANE;
    float* outp = out + (size_t)b * ((size_t)D_MODEL * PLANE) + yx + l;
    #pragma unroll
    for (int i = 0; i < 8; i++) {
        int wd = w * 8 + i;                     // word 0..63 -> channels 2wd, 2wd+1
        u32 u = tile32[l * 65 + wd];
        float2 f = __half22float2(*(__half2*)&u);
        __stcs(outp + (size_t)(2 * wd) * PLANE, f.x);
        __stcs(outp + (size_t)(2 * wd + 1) * PLANE, f.y);
    }
}

extern "C" void kernel_launch(void* const* d_in, const int* in_sizes, int n_in,
                              void* d_out, int out_size) {
    const float* V   = (const float*)d_in[0];
    const float* W0  = (const float*)d_in[1];
    const float* b0  = (const float*)d_in[2];
    const int*   c32 = (const int*)d_in[3];
    float* out = (float*)d_out;

    cudaFuncSetAttribute((const void*)k_gemm,
                         cudaFuncAttributeMaxDynamicSharedMemorySize, GEMM_SMEM);

    // fork/join stream + events (capture-legal; no device memory involved)
    cudaStream_t s1;
    cudaStreamCreateWithFlags(&s1, cudaStreamNonBlocking);
    cudaEvent_t ev[NCHUNK], evJ;
    for (int i = 0; i < NCHUNK; i++)
        cudaEventCreateWithFlags(&ev[i], cudaEventDisableTiming);
    cudaEventCreateWithFlags(&evJ, cudaEventDisableTiming);

    // stream 0: prep + gemm chunks
    k_init<<<1, 2 * NGROUP>>>();
    k_count<<<782, 256>>>(c32);
    k_fill<<<782, 256>>>(c32);
    for (int g = 0; g < NCHUNK; g++) {
        int blocks = (g == NCHUNK - 1) ? (3125 - CBLK * (NCHUNK - 1)) : CBLK;
        k_gemm<<<blocks, 256, GEMM_SMEM>>>(V, W0, b0, CBLK * g);
        cudaEventRecord(ev[g], 0);
    }
    // forked stream: gather chunks, each gated on gemm chunk g+1 (25k-slot slack)
    for (int g = 0; g < NCHUNK; g++) {
        int dep = (g + 1 < NCHUNK) ? (g + 1) : (NCHUNK - 1);
        cudaStreamWaitEvent(s1, ev[dep], 0);
        k_gath<<<GPOSN / 32, 256, 0, s1>>>(out, g * GPOSN);
    }
    cudaEventRecord(evJ, s1);
    cudaStreamWaitEvent((cudaStream_t)0, evJ, 0);   // join before capture ends
}

// round 17
// speedup vs baseline: 1.2210x; 1.2210x over previous
#include <cuda_runtime.h>
#include <cuda_fp16.h>
#include <cstdint>
#include <cstddef>

#define N_VOX   200000
#define C_IN    128
#define D_MODEL 128
#define NY      400
#define NX      400
#define NB      4
#define PLANE   (NY*NX)        /* 160000 */
#define NPOS    (NB*PLANE)     /* 640000 */

#define NTILE   3125           /* 200000 / 64 */
#define GGRID   444            /* 148 SMs x 3 CTAs = one wave */

typedef unsigned int u32;

// ---- scratch (device globals; zero-initialized at module load) ----
__device__ uint4 g_feath4[(size_t)N_VOX * 16];   // 51.2 MB: feat as fp16 (64 half2/row)
__device__ int4  g_inv4[NPOS/4];                 // inv map: 0 = empty, n+1 = voxel n

#define g_feath ((u32*)g_feath4)
#define g_inv   ((int*)g_inv4)

__device__ __forceinline__ uint4 round8h(float4 a, float4 b) {
    uint4 hi;
    __half2 h0 = __float22half2_rn(make_float2(a.x, a.y));
    __half2 h1 = __float22half2_rn(make_float2(a.z, a.w));
    __half2 h2 = __float22half2_rn(make_float2(b.x, b.y));
    __half2 h3 = __float22half2_rn(make_float2(b.z, b.w));
    hi.x = *(u32*)&h0; hi.y = *(u32*)&h1; hi.z = *(u32*)&h2; hi.w = *(u32*)&h3;
    return hi;
}

__device__ __forceinline__ u32 smem_u32(const void* p) {
    u32 a;
    asm("{ .reg .u64 t; cvta.to.shared.u64 t, %1; cvt.u32.u64 %0, t; }"
        : "=r"(a) : "l"(p));
    return a;
}
__device__ __forceinline__ void ldsm_x4(u32 addr, u32& r0, u32& r1, u32& r2, u32& r3) {
    asm volatile("ldmatrix.sync.aligned.m8n8.x4.shared.b16 {%0,%1,%2,%3}, [%4];"
                 : "=r"(r0), "=r"(r1), "=r"(r2), "=r"(r3) : "r"(addr));
}
__device__ __forceinline__ void mma16816h(float* c, const u32* a, const u32* b) {
    asm volatile(
        "mma.sync.aligned.m16n8k16.row.col.f32.f16.f16.f32 "
        "{%0,%1,%2,%3}, {%4,%5,%6,%7}, {%8,%9}, {%0,%1,%2,%3};"
        : "+f"(c[0]), "+f"(c[1]), "+f"(c[2]), "+f"(c[3])
        : "r"(a[0]), "r"(a[1]), "r"(a[2]), "r"(a[3]), "r"(b[0]), "r"(b[1]));
}

// ---- kernel 1: persistent GEMM + inline scatter + one-time W convert ----
// feat = fp16(V) @ fp16(W0)^T + b0, stored fp16. Grid = 444 persistent CTAs
// (one wave at 3/SM); each stages W ONCE, then loops ~7 tiles with A double-
// buffering (next tile's LDG/STS overlaps current tile's MMA).
// smem tiles stride 136 h16: ldmatrix banks (4r+c)%32, conflict-free.
#define TSTRIDE 136
#define A_ELEMS (64 * TSTRIDE)    /* 17408 B */
#define W_ELEMS (128 * TSTRIDE)   /* 34816 B */
#define GEMM_SMEM ((2 * A_ELEMS + W_ELEMS) * 2)   /* 69632 B; x3 = 208.9 KB/SM */

__global__ __launch_bounds__(256, 3) void k_gemm(const float* __restrict__ V,
                                                 const float* __restrict__ W0,
                                                 const float* __restrict__ b0,
                                                 const int* __restrict__ c32) {
    extern __shared__ __align__(16) __half sm[];
    __half* Abuf[2] = { sm, sm + A_ELEMS };
    __half* Wh = sm + 2 * A_ELEMS;

    int tid = threadIdx.x, w = tid >> 5, lane = tid & 31;

    // coors dtype detect (int64 words [b,0,0,0,y,0,x,0] -> odd words zero)
    int dv = c32[8 * lane + 3] | c32[8 * lane + 7];
    bool is64 = (__ballot_sync(0xFFFFFFFF, dv != 0) == 0);

    // stage W once: W0 f32 (64KB, L2-resident) -> fp16 swizzled
    #pragma unroll
    for (int i = 0; i < 8; i++) {
        int x = tid + 256 * i;                  // 2048 groups of 8
        int n = x >> 4, j = x & 15;
        const float4* src = (const float4*)(W0 + n * 128 + 8 * j);
        *(uint4*)(Wh + n * TSTRIDE + 8 * j) = round8h(src[0], src[1]);
    }

    int wm = w & 1, wn = w >> 1;                // 2m x 4n warp grid
    int a_row = 32 * wm + (lane & 15);
    int b_row = 32 * wn + (lane & 15);
    int c_half = (lane >> 4) << 3;
    u32 wh_base = smem_u32(Wh);
    int cp = 2 * (lane & 3);

    // stage first tile into buffer 0 (+ its scatter)
    int t0 = blockIdx.x;
    {
        int row_base = 64 * t0;
        if (tid < 64) {
            int n = row_base + tid;
            int b, y, x;
            if (is64) { b = c32[8*n + 0]; y = c32[8*n + 4]; x = c32[8*n + 6]; }
            else      { b = c32[4*n + 0]; y = c32[4*n + 2]; x = c32[4*n + 3]; }
            g_inv[b * PLANE + y * NX + x] = n + 1;
        }
        #pragma unroll
        for (int i = 0; i < 4; i++) {
            int x = tid + 256 * i;
            int r = x >> 4, j = x & 15;
            const float4* src = (const float4*)(V + (size_t)(row_base + r) * 128 + 8 * j);
            float4 a = __ldcs(src), b = __ldcs(src + 1);
            *(uint4*)(Abuf[0] + r * TSTRIDE + 8 * j) = round8h(a, b);
        }
    }
    __syncthreads();

    int cur = 0;
    for (int t = t0; t < NTILE; t += GGRID, cur ^= 1) {
        // prefetch next tile into the other buffer (overlaps MMA below)
        int tn = t + GGRID;
        if (tn < NTILE) {
            int rbn = 64 * tn;
            if (tid < 64) {
                int n = rbn + tid;
                int b, y, x;
                if (is64) { b = c32[8*n + 0]; y = c32[8*n + 4]; x = c32[8*n + 6]; }
                else      { b = c32[4*n + 0]; y = c32[4*n + 2]; x = c32[4*n + 3]; }
                g_inv[b * PLANE + y * NX + x] = n + 1;
            }
            __half* An = Abuf[cur ^ 1];
            #pragma unroll
            for (int i = 0; i < 4; i++) {
                int x = tid + 256 * i;
                int r = x >> 4, j = x & 15;
                const float4* src = (const float4*)(V + (size_t)(rbn + r) * 128 + 8 * j);
                float4 a = __ldcs(src), b = __ldcs(src + 1);
                *(uint4*)(An + r * TSTRIDE + 8 * j) = round8h(a, b);
            }
        }

        // MMA on current buffer
        u32 ah_base = smem_u32(Abuf[cur]);
        float acc[2][4][4];
        #pragma unroll
        for (int mt = 0; mt < 2; mt++)
            #pragma unroll
            for (int nt = 0; nt < 4; nt++)
                #pragma unroll
                for (int q = 0; q < 4; q++) acc[mt][nt][q] = 0.f;

        #pragma unroll
        for (int ks = 0; ks < 8; ks++) {
            int kb = 16 * ks + c_half;
            u32 aH[2][4], bH[4][2];
            #pragma unroll
            for (int mt = 0; mt < 2; mt++) {
                u32 off = (u32)(((a_row + 16 * mt) * TSTRIDE + kb) * 2);
                ldsm_x4(ah_base + off, aH[mt][0], aH[mt][1], aH[mt][2], aH[mt][3]);
            }
            #pragma unroll
            for (int q = 0; q < 2; q++) {
                u32 off = (u32)(((b_row + 16 * q) * TSTRIDE + kb) * 2);
                u32 r0, r1, r2, r3;
                ldsm_x4(wh_base + off, r0, r1, r2, r3);
                bH[2*q][0] = r0; bH[2*q+1][0] = r1; bH[2*q][1] = r2; bH[2*q+1][1] = r3;
            }
            #pragma unroll
            for (int mt = 0; mt < 2; mt++)
                #pragma unroll
                for (int nt = 0; nt < 4; nt++)
                    mma16816h(acc[mt][nt], aH[mt], bH[nt]);
        }

        // epilogue: bias + fp16 pack; u32 stores (16B per quarter-warp)
        int row_base = 64 * t;
        #pragma unroll
        for (int nt = 0; nt < 4; nt++) {
            int c = 32 * wn + 8 * nt + cp;
            float blo = __ldg(b0 + c), bhi = __ldg(b0 + c + 1);
            #pragma unroll
            for (int mt = 0; mt < 2; mt++) {
                int r0 = row_base + 32 * wm + 16 * mt + (lane >> 2);
                __half2 h0 = __float22half2_rn(
                    make_float2(acc[mt][nt][0] + blo, acc[mt][nt][1] + bhi));
                __half2 h1 = __float22half2_rn(
                    make_float2(acc[mt][nt][2] + blo, acc[mt][nt][3] + bhi));
                g_feath[(size_t)r0 * 64 + (c >> 1)]       = *(u32*)&h0;
                g_feath[(size_t)(r0 + 8) * 64 + (c >> 1)] = *(u32*)&h1;
            }
        }
        __syncthreads();   // buffer handoff: all reads of Abuf[cur] done
    }
}

// ---- kernel 2: gather + transpose into [B, C, NY, NX] (r11, at write floor) ----
__global__ __launch_bounds__(256) void k_gather(float* __restrict__ out) {
    __shared__ int s_inv[32];
    __shared__ u32 tile32[32 * 65];
    int base = blockIdx.x * 32;
    int tid = threadIdx.x;
    if (tid < 32) s_inv[tid] = g_inv[base + tid];
    __syncthreads();
    int w = tid >> 5, l = tid & 31;
    #pragma unroll
    for (int i = 0; i < 4; i++) {
        int p = (w << 2) | i;
        int n = s_inv[p];                       // warp-uniform branch
        if (n > 0) {
            const u32* fr = g_feath + (size_t)(n - 1) * 64;
            tile32[p * 65 + l]      = fr[l];
            tile32[p * 65 + 32 + l] = fr[l + 32];
        } else {
            tile32[p * 65 + l]      = 0u;
            tile32[p * 65 + 32 + l] = 0u;
        }
    }
    __syncthreads();
    int b  = base / PLANE;
    int yx = base - b * PLANE;
    float* outp = out + (size_t)b * ((size_t)D_MODEL * PLANE) + yx + l;
    #pragma unroll
    for (int i = 0; i < 8; i++) {
        int wd = w * 8 + i;                     // word 0..63 -> channels 2wd, 2wd+1
        u32 u = tile32[l * 65 + wd];
        float2 f = __half22float2(*(__half2*)&u);
        __stcs(outp + (size_t)(2 * wd) * PLANE, f.x);
        __stcs(outp + (size_t)(2 * wd + 1) * PLANE, f.y);
    }
}

extern "C" void kernel_launch(void* const* d_in, const int* in_sizes, int n_in,
                              void* d_out, int out_size) {
    const float* V   = (const float*)d_in[0];
    const float* W0  = (const float*)d_in[1];
    const float* b0  = (const float*)d_in[2];
    const int*   c32 = (const int*)d_in[3];
    float* out = (float*)d_out;

    cudaFuncSetAttribute((const void*)k_gemm,
                         cudaFuncAttributeMaxDynamicSharedMemorySize, GEMM_SMEM);

    k_gemm<<<GGRID, 256, GEMM_SMEM>>>(V, W0, b0, c32);
    k_gather<<<NPOS / 32, 256>>>(out);
}